// round 9
// baseline (speedup 1.0000x reference)
#include <cuda_runtime.h>
#include <cuda_bf16.h>
#include <cstdint>

// Problem constants
#define BB 32
#define LL 4096
#define DD 512
#define MODES 64
#define NK 128          // 2*MODES (real rows + imag rows)

// ---------------------------------------------------------------------------
// Static device scratch
// ---------------------------------------------------------------------------
__device__ float g_F1[NK * 2048];                // folded fwd tables [128][2048], l=j+1 (tf32)
__device__ float g_S3F[1024 * 128];              // folded inv tables [l][c]: c<32 cosE,<64 cosO,<96 -sinE,<128 -sinO
__device__ float g_Wt[2ull * MODES * DD * DD];   // [ri][m][d][e] (tf32)
__device__ float g_Q[BB * NK * DD];              // [b][row][d] (tf32)
__device__ float g_Am[BB * NK * DD];             // [b][k][e] (tf32)

// ---------------------------------------------------------------------------
// Helpers
// ---------------------------------------------------------------------------
__device__ __forceinline__ uint32_t f2tf(float f) {
    uint32_t u;
    asm("cvt.rna.tf32.f32 %0, %1;" : "=r"(u) : "f"(f));
    return u;
}
__device__ __forceinline__ float f2tf_f(float f) { return __uint_as_float(f2tf(f)); }

__device__ __forceinline__ void mma_tf32(float c[4],
                                         uint32_t a0, uint32_t a1, uint32_t a2, uint32_t a3,
                                         uint32_t b0, uint32_t b1) {
    asm volatile(
        "mma.sync.aligned.m16n8k8.row.col.f32.tf32.tf32.f32 "
        "{%0,%1,%2,%3}, {%4,%5,%6,%7}, {%8,%9}, {%0,%1,%2,%3};"
        : "+f"(c[0]), "+f"(c[1]), "+f"(c[2]), "+f"(c[3])
        : "r"(a0), "r"(a1), "r"(a2), "r"(a3), "r"(b0), "r"(b1));
}

__device__ __forceinline__ void cp16(uint32_t dst_smem, const void* src) {
    asm volatile("cp.async.cg.shared.global [%0], [%1], 16;" :: "r"(dst_smem), "l"(src));
}
__device__ __forceinline__ void cp_commit() { asm volatile("cp.async.commit_group;"); }

// ---------------------------------------------------------------------------
// Init: all twiddle tables in one launch (tf32-rounded).
// ---------------------------------------------------------------------------
#define F1_CNT (NK * 2048)
#define S3F_CNT (1024 * 128)

__global__ void fno_init() {
    int idx = blockIdx.x * blockDim.x + threadIdx.x;
    if (idx < F1_CNT) {
        int row = idx >> 11;          // 0..127
        int j   = idx & 2047;
        int l   = j + 1;              // 1..2048
        int m   = row & (MODES - 1);
        int r   = (m * l) & (LL - 1);
        float s, c;
        sincospif((float)r * (1.0f / 2048.0f), &s, &c);
        g_F1[row * 2048 + j] = f2tf_f((row < MODES) ? c : -s);
    } else if (idx < F1_CNT + S3F_CNT) {
        int i2 = idx - F1_CNT;
        int l  = i2 >> 7;             // 0..1023
        int cc = i2 & 127;
        int grp = cc >> 5;            // 0 cosE, 1 cosO, 2 -sinE, 3 -sinO
        int m  = ((cc & 31) << 1) + (grp & 1);
        int r  = (m * l) & (LL - 1);
        float s, c;
        sincospif((float)r * (1.0f / 2048.0f), &s, &c);
        g_S3F[l * 128 + cc] = f2tf_f((grp < 2) ? c : -s);
    }
}

// ---------------------------------------------------------------------------
// Weight transpose (standalone, light): Wt[ri][m][d][e] = tf32(w_ri[d][e][m])
// ---------------------------------------------------------------------------
__global__ void fno_transpose_w(const float* __restrict__ wr,
                                const float* __restrict__ wi) {
    __shared__ float t[2][32][33];
    int d  = blockIdx.z;
    int e0 = blockIdx.x * 32;
    int m0 = blockIdx.y * 32;
    int tx = threadIdx.x, ty = threadIdx.y;
    size_t src_base = ((size_t)d * DD) * MODES + m0;
    for (int i = ty; i < 32; i += 8) {
        t[0][i][tx] = wr[src_base + (size_t)(e0 + i) * MODES + tx];
        t[1][i][tx] = wi[src_base + (size_t)(e0 + i) * MODES + tx];
    }
    __syncthreads();
    for (int i = ty; i < 32; i += 8) {
        size_t dst0 = (((size_t)(m0 + i)) * DD + d) * DD + e0 + tx;
        g_Wt[dst0]                           = f2tf_f(t[0][tx][i]);
        g_Wt[dst0 + (size_t)MODES * DD * DD] = f2tf_f(t[1][tx][i]);
    }
}

// ===========================================================================
// Stage 1 (folded, tf32 MMA, BN=64): per-batch
//   Qr[64,512] = cosF[64,2048] x P[2048,512]   (+ q[0,:] correction)
//   Qi[64,512] = (-sinF)[64,2048] x D[2048,512]
// grid (8 n-tiles, 32 b), block 256 (8 warps: wm {0=Qr,1=Qi}, wn 0..3 x16e).
// Warp tile 64x16. 2 CTAs/SM target.
// ===========================================================================
#define F1_A_F (128 * 36)
#define F1_B_F (32 * 72)
#define S1F_SMEM ((2 * F1_A_F + 4 * F1_B_F) * 4)   // 73728

__global__ __launch_bounds__(256, 2) void fno_stage1_fold(const float* __restrict__ q) {
    extern __shared__ float sm[];
    float* Bbase = sm + 2 * F1_A_F;
    const int b  = blockIdx.y;
    const int n0 = blockIdx.x * 64;
    const float* qb = q + (size_t)b * LL * DD;
    const int tid = threadIdx.x;
    const int warp = tid >> 5, lane = tid & 31;
    const int wm = warp >> 2, wn = warp & 3;
    const int gid = lane >> 2, tig = lane & 3;
    const uint32_t smu = (uint32_t)__cvta_generic_to_shared(sm);

    float acc[4][2][4];
#pragma unroll
    for (int i = 0; i < 4; i++)
#pragma unroll
        for (int j = 0; j < 2; j++)
#pragma unroll
            for (int k = 0; k < 4; k++) acc[i][j][k] = 0.0f;

    // per-thread B-load jobs: 2 x (row j, col c4 of 16)
    float4 v1[2], v2[2];
    auto ldB = [&](int k0) {
#pragma unroll
        for (int i = 0; i < 2; i++) {
            int idx = tid + i * 256;
            int j = idx >> 4, c4 = idx & 15;
            int l = k0 + j + 1;
            v1[i] = *(const float4*)&qb[(size_t)l * DD + n0 + c4 * 4];
            if (l == 2048) {
                v2[i] = make_float4(0.f, 0.f, 0.f, 0.f);
            } else {
                v2[i] = *(const float4*)&qb[(size_t)(LL - l) * DD + n0 + c4 * 4];
            }
        }
    };
    auto stB = [&](int buf) {
        float* P = Bbase + buf * 2 * F1_B_F;
        float* Dn = P + F1_B_F;
#pragma unroll
        for (int i = 0; i < 2; i++) {
            int idx = tid + i * 256;
            int j = idx >> 4, c4 = idx & 15;
            float4 p, d;
            p.x = f2tf_f(v1[i].x + v2[i].x);  d.x = f2tf_f(v1[i].x - v2[i].x);
            p.y = f2tf_f(v1[i].y + v2[i].y);  d.y = f2tf_f(v1[i].y - v2[i].y);
            p.z = f2tf_f(v1[i].z + v2[i].z);  d.z = f2tf_f(v1[i].z - v2[i].z);
            p.w = f2tf_f(v1[i].w + v2[i].w);  d.w = f2tf_f(v1[i].w - v2[i].w);
            *(float4*)&P[j * 72 + c4 * 4]  = p;
            *(float4*)&Dn[j * 72 + c4 * 4] = d;
        }
    };
    auto cpA = [&](int buf, int k0) {
        uint32_t aB = smu + buf * F1_A_F * 4;
#pragma unroll
        for (int i = 0; i < 4; i++) {
            int idx = tid + i * 256;
            int row = idx >> 3, c4 = idx & 7;
            cp16(aB + (row * 36 + c4 * 4) * 4, &g_F1[row * 2048 + k0 + c4 * 4]);
        }
        cp_commit();
    };

    cpA(0, 0);
    ldB(0);
    const int NT = 64;
    for (int kt = 0; kt < NT; kt++) {
        int buf = kt & 1;
        stB(buf);
        if (kt + 1 < NT) {
            cpA(buf ^ 1, (kt + 1) * 32);
            asm volatile("cp.async.wait_group 1;");
        } else {
            asm volatile("cp.async.wait_group 0;");
        }
        __syncthreads();
        if (kt + 1 < NT) ldB((kt + 1) * 32);

        const float* As = sm + buf * F1_A_F;
        const float* Bs = Bbase + buf * 2 * F1_B_F + wm * F1_B_F;  // P or D
#pragma unroll
        for (int ks = 0; ks < 4; ks++) {
            uint32_t a[4][4];
#pragma unroll
            for (int tm = 0; tm < 4; tm++) {
                const float* ap = As + (wm * 64 + tm * 16 + gid) * 36 + ks * 8 + tig;
                a[tm][0] = __float_as_uint(ap[0]);
                a[tm][1] = __float_as_uint(ap[8 * 36]);
                a[tm][2] = __float_as_uint(ap[4]);
                a[tm][3] = __float_as_uint(ap[8 * 36 + 4]);
            }
            uint32_t bf[2][2];
#pragma unroll
            for (int tn = 0; tn < 2; tn++) {
                const float* bp = Bs + (ks * 8 + tig) * 72 + wn * 16 + tn * 8 + gid;
                bf[tn][0] = __float_as_uint(bp[0]);
                bf[tn][1] = __float_as_uint(bp[4 * 72]);
            }
#pragma unroll
            for (int tm = 0; tm < 4; tm++)
#pragma unroll
                for (int tn = 0; tn < 2; tn++)
                    mma_tf32(acc[tm][tn], a[tm][0], a[tm][1], a[tm][2], a[tm][3],
                             bf[tn][0], bf[tn][1]);
        }
        __syncthreads();
    }

#pragma unroll
    for (int tm = 0; tm < 4; tm++) {
        int r = wm * 64 + tm * 16 + gid;
#pragma unroll
        for (int tn = 0; tn < 2; tn++) {
            int c = n0 + wn * 16 + tn * 8 + tig * 2;
            float c0 = 0.f, c1 = 0.f;
            if (wm == 0) { c0 = qb[c]; c1 = qb[c + 1]; }
            float2 v0 = make_float2(f2tf_f(acc[tm][tn][0] + c0),
                                    f2tf_f(acc[tm][tn][1] + c1));
            float2 v1s = make_float2(f2tf_f(acc[tm][tn][2] + c0),
                                     f2tf_f(acc[tm][tn][3] + c1));
            *(float2*)&g_Q[((size_t)b * NK + r) * DD + c]     = v0;
            *(float2*)&g_Q[((size_t)b * NK + r + 8) * DD + c] = v1s;
        }
    }
}

// ---------------------------------------------------------------------------
// Stage 2 (tf32 mma.sync, unchanged): per-mode complex GEMM.
// ---------------------------------------------------------------------------
#define S2_ASZ (64 * 36)
#define S2_BSZ (64 * 136)
#define S2_BUF (S2_ASZ + S2_BSZ)
#define S2_SMEM (2 * S2_BUF * 4)

__global__ __launch_bounds__(256) void fno_stage2_mma() {
    extern __shared__ float sm[];
    const int m  = blockIdx.y;
    const int e0 = blockIdx.x * 128;
    const int tid = threadIdx.x;
    const int warp = tid >> 5, lane = tid & 31;
    const int wm = warp >> 2;
    const int wn = warp & 3;
    const int gid = lane >> 2, tig = lane & 3;
    const uint32_t smem_u = (uint32_t)__cvta_generic_to_shared(sm);

    float accR[4][4], accI[4][4];
#pragma unroll
    for (int i = 0; i < 4; i++)
#pragma unroll
        for (int j = 0; j < 4; j++) { accR[i][j] = 0.0f; accI[i][j] = 0.0f; }

    auto load_tiles = [&](int buf, int d0) {
        uint32_t aB = smem_u + buf * S2_BUF * 4;
        uint32_t bB = aB + S2_ASZ * 4;
#pragma unroll
        for (int i = 0; i < 2; i++) {
            int idx = tid + i * 256;
            int row = idx >> 3, c4 = idx & 7;
            int ri = row >> 5, bb = row & 31;
            cp16(aB + (row * 36 + c4 * 4) * 4,
                 &g_Q[((size_t)bb * NK + ri * MODES + m) * DD + d0 + c4 * 4]);
        }
#pragma unroll
        for (int i = 0; i < 8; i++) {
            int idx = tid + i * 256;
            int row = idx >> 5, c4 = idx & 31;
            int ri = row >> 5, dr = row & 31;
            cp16(bB + (row * 136 + c4 * 4) * 4,
                 &g_Wt[(((size_t)ri * MODES + m) * DD + d0 + dr) * DD + e0 + c4 * 4]);
        }
        cp_commit();
    };

    load_tiles(0, 0);
    int buf = 0;
    const int NT = DD / 32;
    for (int kt = 0; kt < NT; kt++) {
        if (kt + 1 < NT) {
            load_tiles(buf ^ 1, (kt + 1) * 32);
            asm volatile("cp.async.wait_group 1;");
        } else {
            asm volatile("cp.async.wait_group 0;");
        }
        __syncthreads();
        const float* As = sm + buf * S2_BUF;
        const float* Bs = As + S2_ASZ;
#pragma unroll
        for (int ks = 0; ks < 4; ks++) {
            uint32_t ar[4], ai[4];
            {
                const float* ap = As + (wm * 16 + gid) * 36 + ks * 8 + tig;
                ar[0] = __float_as_uint(ap[0]);
                ar[1] = __float_as_uint(ap[8 * 36]);
                ar[2] = __float_as_uint(ap[4]);
                ar[3] = __float_as_uint(ap[8 * 36 + 4]);
                const float* aq = ap + 32 * 36;
                ai[0] = __float_as_uint(aq[0]);
                ai[1] = __float_as_uint(aq[8 * 36]);
                ai[2] = __float_as_uint(aq[4]);
                ai[3] = __float_as_uint(aq[8 * 36 + 4]);
            }
#pragma unroll
            for (int tn = 0; tn < 4; tn++) {
                const float* bp = Bs + (ks * 8 + tig) * 136 + wn * 32 + tn * 8 + gid;
                uint32_t br0 = __float_as_uint(bp[0]);
                uint32_t br1 = __float_as_uint(bp[4 * 136]);
                const float* bq = bp + 32 * 136;
                uint32_t bi0 = __float_as_uint(bq[0]);
                uint32_t bi1 = __float_as_uint(bq[4 * 136]);
                mma_tf32(accR[tn], ar[0], ar[1], ar[2], ar[3], br0, br1);
                mma_tf32(accR[tn], ai[0], ai[1], ai[2], ai[3],
                         bi0 ^ 0x80000000u, bi1 ^ 0x80000000u);
                mma_tf32(accI[tn], ar[0], ar[1], ar[2], ar[3], bi0, bi1);
                mma_tf32(accI[tn], ai[0], ai[1], ai[2], ai[3], br0, br1);
            }
        }
        __syncthreads();
        buf ^= 1;
    }

    const float cscale = (m == 0) ? (1.0f / (float)LL) : (2.0f / (float)LL);
#pragma unroll
    for (int tn = 0; tn < 4; tn++) {
        int c = e0 + wn * 32 + tn * 8 + tig * 2;
        int b0r = wm * 16 + gid;
        float2 r0 = make_float2(f2tf_f(cscale * accR[tn][0]), f2tf_f(cscale * accR[tn][1]));
        float2 r1 = make_float2(f2tf_f(cscale * accR[tn][2]), f2tf_f(cscale * accR[tn][3]));
        float2 i0 = make_float2(f2tf_f(cscale * accI[tn][0]), f2tf_f(cscale * accI[tn][1]));
        float2 i1 = make_float2(f2tf_f(cscale * accI[tn][2]), f2tf_f(cscale * accI[tn][3]));
        *(float2*)&g_Am[((size_t)b0r * NK + m) * DD + c]               = r0;
        *(float2*)&g_Am[((size_t)(b0r + 8) * NK + m) * DD + c]         = r1;
        *(float2*)&g_Am[((size_t)b0r * NK + MODES + m) * DD + c]       = i0;
        *(float2*)&g_Am[((size_t)(b0r + 8) * NK + MODES + m) * DD + c] = i1;
    }
}

// ===========================================================================
// Stage 3 (double-folded, tf32 MMA, BN=64): for l in [0,1024):
//   out[l] = CE+CO+SE+SO ; out[2048-l] = CE-CO-SE+SO
//   out[2048+l] = CE-CO+SE-SO ; out[4096-l] = CE+CO-SE-SO (l>0)
// grid (8 e-tiles, 16 l-tiles, 32 b), block 256. BM=64(l) BN=64(e) K=128.
// Warp tile 32x16; 2 CTAs/SM target.
// ===========================================================================
#define T3_ASZ (64 * 132)
#define T3_BSZ (128 * 72)
#define T3_SMEM ((T3_ASZ + T3_BSZ) * 4)    // 70656

__global__ __launch_bounds__(256, 2) void fno_stage3_fold2(float* __restrict__ out) {
    extern __shared__ float sm[];
    const int b  = blockIdx.z;
    const int l0 = blockIdx.y * 64;
    const int n0 = blockIdx.x * 64;
    const int tid = threadIdx.x;
    const int warp = tid >> 5, lane = tid & 31;
    const int wm = warp >> 2, wn = warp & 3;      // wm 0..1 (32 l-rows), wn 0..3 (16 e)
    const int gid = lane >> 2, tig = lane & 3;
    const uint32_t smem_u = (uint32_t)__cvta_generic_to_shared(sm);
    const float* As = sm;
    const float* Bs = sm + T3_ASZ;

    {
        uint32_t aB = smem_u;
        uint32_t bB = smem_u + T3_ASZ * 4;
#pragma unroll
        for (int i = 0; i < 8; i++) {      // A: 64 rows x 32 float4
            int idx = tid + i * 256;
            int row = idx >> 5, c4 = idx & 31;
            cp16(aB + (row * 132 + c4 * 4) * 4, &g_S3F[(l0 + row) * 128 + c4 * 4]);
        }
#pragma unroll
        for (int i = 0; i < 8; i++) {      // B: 128 rows x 16 float4, row-permuted
            int idx = tid + i * 256;
            int row = idx >> 4, c4 = idx & 15;
            int ri = row >> 6, rr = row & 63;
            int srow = ri * 64 + ((rr & 31) << 1) + (rr >> 5);
            cp16(bB + (row * 72 + c4 * 4) * 4,
                 &g_Am[((size_t)b * NK + srow) * DD + n0 + c4 * 4]);
        }
        cp_commit();
        asm volatile("cp.async.wait_group 0;");
        __syncthreads();
    }

    float aCE[2][2][4], aCO[2][2][4], aSE[2][2][4], aSO[2][2][4];
#pragma unroll
    for (int i = 0; i < 2; i++)
#pragma unroll
        for (int j = 0; j < 2; j++)
#pragma unroll
            for (int k = 0; k < 4; k++) {
                aCE[i][j][k] = 0.0f; aCO[i][j][k] = 0.0f;
                aSE[i][j][k] = 0.0f; aSO[i][j][k] = 0.0f;
            }

#pragma unroll
    for (int ks = 0; ks < 16; ks++) {
        uint32_t a[2][4];
#pragma unroll
        for (int tm = 0; tm < 2; tm++) {
            const float* ap = As + (wm * 32 + tm * 16 + gid) * 132 + ks * 8 + tig;
            a[tm][0] = __float_as_uint(ap[0]);
            a[tm][1] = __float_as_uint(ap[8 * 132]);
            a[tm][2] = __float_as_uint(ap[4]);
            a[tm][3] = __float_as_uint(ap[8 * 132 + 4]);
        }
        uint32_t bf[2][2];
#pragma unroll
        for (int tn = 0; tn < 2; tn++) {
            const float* bp = Bs + (ks * 8 + tig) * 72 + wn * 16 + tn * 8 + gid;
            bf[tn][0] = __float_as_uint(bp[0]);
            bf[tn][1] = __float_as_uint(bp[4 * 72]);
        }
        if (ks < 4) {
#pragma unroll
            for (int tm = 0; tm < 2; tm++)
#pragma unroll
                for (int tn = 0; tn < 2; tn++)
                    mma_tf32(aCE[tm][tn], a[tm][0], a[tm][1], a[tm][2], a[tm][3],
                             bf[tn][0], bf[tn][1]);
        } else if (ks < 8) {
#pragma unroll
            for (int tm = 0; tm < 2; tm++)
#pragma unroll
                for (int tn = 0; tn < 2; tn++)
                    mma_tf32(aCO[tm][tn], a[tm][0], a[tm][1], a[tm][2], a[tm][3],
                             bf[tn][0], bf[tn][1]);
        } else if (ks < 12) {
#pragma unroll
            for (int tm = 0; tm < 2; tm++)
#pragma unroll
                for (int tn = 0; tn < 2; tn++)
                    mma_tf32(aSE[tm][tn], a[tm][0], a[tm][1], a[tm][2], a[tm][3],
                             bf[tn][0], bf[tn][1]);
        } else {
#pragma unroll
            for (int tm = 0; tm < 2; tm++)
#pragma unroll
                for (int tn = 0; tn < 2; tn++)
                    mma_tf32(aSO[tm][tn], a[tm][0], a[tm][1], a[tm][2], a[tm][3],
                             bf[tn][0], bf[tn][1]);
        }
    }

    float* ob = out + (size_t)b * LL * DD;
#pragma unroll
    for (int tm = 0; tm < 2; tm++) {
        int lA = l0 + wm * 32 + tm * 16 + gid;
#pragma unroll
        for (int tn = 0; tn < 2; tn++) {
            int c = n0 + wn * 16 + tn * 8 + tig * 2;
#pragma unroll
            for (int h = 0; h < 2; h++) {
                int l = lA + h * 8;
                float ce0 = aCE[tm][tn][h * 2],     ce1 = aCE[tm][tn][h * 2 + 1];
                float co0 = aCO[tm][tn][h * 2],     co1 = aCO[tm][tn][h * 2 + 1];
                float se0 = aSE[tm][tn][h * 2],     se1 = aSE[tm][tn][h * 2 + 1];
                float so0 = aSO[tm][tn][h * 2],     so1 = aSO[tm][tn][h * 2 + 1];
                *(float2*)&ob[(size_t)l * DD + c] =
                    make_float2(ce0 + co0 + se0 + so0, ce1 + co1 + se1 + so1);
                *(float2*)&ob[(size_t)(2048 - l) * DD + c] =
                    make_float2(ce0 - co0 - se0 + so0, ce1 - co1 - se1 + so1);
                *(float2*)&ob[(size_t)(2048 + l) * DD + c] =
                    make_float2(ce0 - co0 + se0 - so0, ce1 - co1 + se1 - so1);
                if (l > 0)
                    *(float2*)&ob[(size_t)(LL - l) * DD + c] =
                        make_float2(ce0 + co0 - se0 - so0, ce1 + co1 - se1 - so1);
            }
        }
    }
}

// ---------------------------------------------------------------------------
// Rows l=1024 and l=3072 (not covered by the double fold)
// ---------------------------------------------------------------------------
__global__ void fno_rows_special(float* __restrict__ out) {
    int b = blockIdx.y;
    int e = blockIdx.x * 128 + threadIdx.x;
    float C = 0.0f, S = 0.0f;
#pragma unroll
    for (int j = 0; j < 32; j++) {
        float sgn = (j & 1) ? -1.0f : 1.0f;
        C += sgn * g_Am[((size_t)b * NK + 2 * j) * DD + e];
        S -= sgn * g_Am[((size_t)b * NK + MODES + 2 * j + 1) * DD + e];
    }
    out[((size_t)b * LL + 1024) * DD + e] = C + S;
    out[((size_t)b * LL + 3072) * DD + e] = C - S;
}

// ---------------------------------------------------------------------------
// Launch: transpose forked onto side stream (overlaps stage1);
// rows_special forked onto side stream (overlaps stage3).
// ---------------------------------------------------------------------------
extern "C" void kernel_launch(void* const* d_in, const int* in_sizes, int n_in,
                              void* d_out, int out_size) {
    (void)in_sizes; (void)n_in; (void)out_size;
    const float* q  = (const float*)d_in[0];
    const float* wr = (const float*)d_in[1];
    const float* wi = (const float*)d_in[2];
    float* out = (float*)d_out;

    static bool init_done = false;
    static cudaStream_t s_side;
    static cudaEvent_t ev_fork, ev_join, ev_fork2, ev_join2;
    if (!init_done) {
        cudaFuncSetAttribute(fno_stage1_fold,
                             cudaFuncAttributeMaxDynamicSharedMemorySize, S1F_SMEM);
        cudaFuncSetAttribute(fno_stage2_mma,
                             cudaFuncAttributeMaxDynamicSharedMemorySize, S2_SMEM);
        cudaFuncSetAttribute(fno_stage3_fold2,
                             cudaFuncAttributeMaxDynamicSharedMemorySize, T3_SMEM);
        cudaStreamCreateWithFlags(&s_side, cudaStreamNonBlocking);
        cudaEventCreateWithFlags(&ev_fork, cudaEventDisableTiming);
        cudaEventCreateWithFlags(&ev_join, cudaEventDisableTiming);
        cudaEventCreateWithFlags(&ev_fork2, cudaEventDisableTiming);
        cudaEventCreateWithFlags(&ev_join2, cudaEventDisableTiming);
        init_done = true;
    }

    // main stream: tables (stage1/stage3 dependency)
    fno_init<<<(F1_CNT + S3F_CNT + 255) / 256, 256>>>();

    // fork: transpose on side stream, concurrent with stage1
    cudaEventRecord(ev_fork, 0);
    cudaStreamWaitEvent(s_side, ev_fork, 0);
    fno_transpose_w<<<dim3(16, 2, 512), dim3(32, 8), 0, s_side>>>(wr, wi);

    fno_stage1_fold<<<dim3(8, 32), 256, S1F_SMEM>>>(q);

    // join: stage2 needs both g_Q (main) and g_Wt (side)
    cudaEventRecord(ev_join, s_side);
    cudaStreamWaitEvent(0, ev_join, 0);

    fno_stage2_mma<<<dim3(4, 64), 256, S2_SMEM>>>();

    // fork: rows_special on side stream, concurrent with stage3
    cudaEventRecord(ev_fork2, 0);
    cudaStreamWaitEvent(s_side, ev_fork2, 0);
    fno_rows_special<<<dim3(4, 32), 128, 0, s_side>>>(out);

    fno_stage3_fold2<<<dim3(8, 16, 32), 256, T3_SMEM>>>(out);

    // join: out complete on main stream
    cudaEventRecord(ev_join2, s_side);
    cudaStreamWaitEvent(0, ev_join2, 0);
}

// round 10
// speedup vs baseline: 1.0320x; 1.0320x over previous
#include <cuda_runtime.h>
#include <cuda_bf16.h>
#include <cuda_fp16.h>
#include <cstdint>

// Problem constants
#define BB 32
#define LL 4096
#define DD 512
#define MODES 64
#define NK 128          // 2*MODES (real rows + imag rows)
#define WSCALE 16384.0f // 2^14 fp16 range scaling for weights

// ---------------------------------------------------------------------------
// Static device scratch
// ---------------------------------------------------------------------------
__device__ float  g_F1[NK * 2048];               // folded fwd tables [128][2048], l=j+1 (tf32)
__device__ float  g_S3F[1024 * 128];             // folded inv tables [l][c]: c<32 cosE,<64 cosO,<96 -sinE,<128 -sinO
__device__ __half g_WtH[2ull * MODES * DD * DD]; // [ri][m][d][e] fp16, scaled by 2^14
__device__ float  g_Q[BB * NK * DD];             // [b][row][d] (tf32)
__device__ float  g_Am[BB * NK * DD];            // [b][k][e] (tf32)

// ---------------------------------------------------------------------------
// Helpers
// ---------------------------------------------------------------------------
__device__ __forceinline__ uint32_t f2tf(float f) {
    uint32_t u;
    asm("cvt.rna.tf32.f32 %0, %1;" : "=r"(u) : "f"(f));
    return u;
}
__device__ __forceinline__ float f2tf_f(float f) { return __uint_as_float(f2tf(f)); }

__device__ __forceinline__ void mma_tf32(float c[4],
                                         uint32_t a0, uint32_t a1, uint32_t a2, uint32_t a3,
                                         uint32_t b0, uint32_t b1) {
    asm volatile(
        "mma.sync.aligned.m16n8k8.row.col.f32.tf32.tf32.f32 "
        "{%0,%1,%2,%3}, {%4,%5,%6,%7}, {%8,%9}, {%0,%1,%2,%3};"
        : "+f"(c[0]), "+f"(c[1]), "+f"(c[2]), "+f"(c[3])
        : "r"(a0), "r"(a1), "r"(a2), "r"(a3), "r"(b0), "r"(b1));
}

__device__ __forceinline__ void cp16(uint32_t dst_smem, const void* src) {
    asm volatile("cp.async.cg.shared.global [%0], [%1], 16;" :: "r"(dst_smem), "l"(src));
}
__device__ __forceinline__ void cp_commit() { asm volatile("cp.async.commit_group;"); }

// ---------------------------------------------------------------------------
// Init: all twiddle tables in one launch (tf32-rounded).
// ---------------------------------------------------------------------------
#define F1_CNT (NK * 2048)
#define S3F_CNT (1024 * 128)

__global__ void fno_init() {
    int idx = blockIdx.x * blockDim.x + threadIdx.x;
    if (idx < F1_CNT) {
        int row = idx >> 11;          // 0..127
        int j   = idx & 2047;
        int l   = j + 1;              // 1..2048
        int m   = row & (MODES - 1);
        int r   = (m * l) & (LL - 1);
        float s, c;
        sincospif((float)r * (1.0f / 2048.0f), &s, &c);
        g_F1[row * 2048 + j] = f2tf_f((row < MODES) ? c : -s);
    } else if (idx < F1_CNT + S3F_CNT) {
        int i2 = idx - F1_CNT;
        int l  = i2 >> 7;             // 0..1023
        int cc = i2 & 127;
        int grp = cc >> 5;            // 0 cosE, 1 cosO, 2 -sinE, 3 -sinO
        int m  = ((cc & 31) << 1) + (grp & 1);
        int r  = (m * l) & (LL - 1);
        float s, c;
        sincospif((float)r * (1.0f / 2048.0f), &s, &c);
        g_S3F[l * 128 + cc] = f2tf_f((grp < 2) ? c : -s);
    }
}

// ---------------------------------------------------------------------------
// Weight transpose: WtH[ri][m][d][e] = fp16(w_ri[d][e][m] * 2^14)
// ---------------------------------------------------------------------------
__global__ void fno_transpose_w(const float* __restrict__ wr,
                                const float* __restrict__ wi) {
    __shared__ float t[2][32][33];
    int d  = blockIdx.z;
    int e0 = blockIdx.x * 32;
    int m0 = blockIdx.y * 32;
    int tx = threadIdx.x, ty = threadIdx.y;
    size_t src_base = ((size_t)d * DD) * MODES + m0;
    for (int i = ty; i < 32; i += 8) {
        t[0][i][tx] = wr[src_base + (size_t)(e0 + i) * MODES + tx];
        t[1][i][tx] = wi[src_base + (size_t)(e0 + i) * MODES + tx];
    }
    __syncthreads();
    for (int i = ty; i < 32; i += 8) {
        size_t dst0 = (((size_t)(m0 + i)) * DD + d) * DD + e0 + tx;
        g_WtH[dst0]                           = __float2half_rn(t[0][tx][i] * WSCALE);
        g_WtH[dst0 + (size_t)MODES * DD * DD] = __float2half_rn(t[1][tx][i] * WSCALE);
    }
}

// ===========================================================================
// Stage 1 (folded, tf32 MMA, BN=64): per-batch
//   Qr[64,512] = cosF[64,2048] x P[2048,512]   (+ q[0,:] correction)
//   Qi[64,512] = (-sinF)[64,2048] x D[2048,512]
// grid (8 n-tiles, 32 b), block 256. Warp tile 64x16. 2 CTAs/SM.
// ===========================================================================
#define F1_A_F (128 * 36)
#define F1_B_F (32 * 72)
#define S1F_SMEM ((2 * F1_A_F + 4 * F1_B_F) * 4)   // 73728

__global__ __launch_bounds__(256, 2) void fno_stage1_fold(const float* __restrict__ q) {
    extern __shared__ float sm[];
    float* Bbase = sm + 2 * F1_A_F;
    const int b  = blockIdx.y;
    const int n0 = blockIdx.x * 64;
    const float* qb = q + (size_t)b * LL * DD;
    const int tid = threadIdx.x;
    const int warp = tid >> 5, lane = tid & 31;
    const int wm = warp >> 2, wn = warp & 3;
    const int gid = lane >> 2, tig = lane & 3;
    const uint32_t smu = (uint32_t)__cvta_generic_to_shared(sm);

    float acc[4][2][4];
#pragma unroll
    for (int i = 0; i < 4; i++)
#pragma unroll
        for (int j = 0; j < 2; j++)
#pragma unroll
            for (int k = 0; k < 4; k++) acc[i][j][k] = 0.0f;

    float4 v1[2], v2[2];
    auto ldB = [&](int k0) {
#pragma unroll
        for (int i = 0; i < 2; i++) {
            int idx = tid + i * 256;
            int j = idx >> 4, c4 = idx & 15;
            int l = k0 + j + 1;
            v1[i] = *(const float4*)&qb[(size_t)l * DD + n0 + c4 * 4];
            if (l == 2048) {
                v2[i] = make_float4(0.f, 0.f, 0.f, 0.f);
            } else {
                v2[i] = *(const float4*)&qb[(size_t)(LL - l) * DD + n0 + c4 * 4];
            }
        }
    };
    auto stB = [&](int buf) {
        float* P = Bbase + buf * 2 * F1_B_F;
        float* Dn = P + F1_B_F;
#pragma unroll
        for (int i = 0; i < 2; i++) {
            int idx = tid + i * 256;
            int j = idx >> 4, c4 = idx & 15;
            float4 p, d;
            p.x = f2tf_f(v1[i].x + v2[i].x);  d.x = f2tf_f(v1[i].x - v2[i].x);
            p.y = f2tf_f(v1[i].y + v2[i].y);  d.y = f2tf_f(v1[i].y - v2[i].y);
            p.z = f2tf_f(v1[i].z + v2[i].z);  d.z = f2tf_f(v1[i].z - v2[i].z);
            p.w = f2tf_f(v1[i].w + v2[i].w);  d.w = f2tf_f(v1[i].w - v2[i].w);
            *(float4*)&P[j * 72 + c4 * 4]  = p;
            *(float4*)&Dn[j * 72 + c4 * 4] = d;
        }
    };
    auto cpA = [&](int buf, int k0) {
        uint32_t aB = smu + buf * F1_A_F * 4;
#pragma unroll
        for (int i = 0; i < 4; i++) {
            int idx = tid + i * 256;
            int row = idx >> 3, c4 = idx & 7;
            cp16(aB + (row * 36 + c4 * 4) * 4, &g_F1[row * 2048 + k0 + c4 * 4]);
        }
        cp_commit();
    };

    cpA(0, 0);
    ldB(0);
    const int NT = 64;
    for (int kt = 0; kt < NT; kt++) {
        int buf = kt & 1;
        stB(buf);
        if (kt + 1 < NT) {
            cpA(buf ^ 1, (kt + 1) * 32);
            asm volatile("cp.async.wait_group 1;");
        } else {
            asm volatile("cp.async.wait_group 0;");
        }
        __syncthreads();
        if (kt + 1 < NT) ldB((kt + 1) * 32);

        const float* As = sm + buf * F1_A_F;
        const float* Bs = Bbase + buf * 2 * F1_B_F + wm * F1_B_F;  // P or D
#pragma unroll
        for (int ks = 0; ks < 4; ks++) {
            uint32_t a[4][4];
#pragma unroll
            for (int tm = 0; tm < 4; tm++) {
                const float* ap = As + (wm * 64 + tm * 16 + gid) * 36 + ks * 8 + tig;
                a[tm][0] = __float_as_uint(ap[0]);
                a[tm][1] = __float_as_uint(ap[8 * 36]);
                a[tm][2] = __float_as_uint(ap[4]);
                a[tm][3] = __float_as_uint(ap[8 * 36 + 4]);
            }
            uint32_t bf[2][2];
#pragma unroll
            for (int tn = 0; tn < 2; tn++) {
                const float* bp = Bs + (ks * 8 + tig) * 72 + wn * 16 + tn * 8 + gid;
                bf[tn][0] = __float_as_uint(bp[0]);
                bf[tn][1] = __float_as_uint(bp[4 * 72]);
            }
#pragma unroll
            for (int tm = 0; tm < 4; tm++)
#pragma unroll
                for (int tn = 0; tn < 2; tn++)
                    mma_tf32(acc[tm][tn], a[tm][0], a[tm][1], a[tm][2], a[tm][3],
                             bf[tn][0], bf[tn][1]);
        }
        __syncthreads();
    }

#pragma unroll
    for (int tm = 0; tm < 4; tm++) {
        int r = wm * 64 + tm * 16 + gid;
#pragma unroll
        for (int tn = 0; tn < 2; tn++) {
            int c = n0 + wn * 16 + tn * 8 + tig * 2;
            float c0 = 0.f, c1 = 0.f;
            if (wm == 0) { c0 = qb[c]; c1 = qb[c + 1]; }
            float2 v0 = make_float2(f2tf_f(acc[tm][tn][0] + c0),
                                    f2tf_f(acc[tm][tn][1] + c1));
            float2 v1s = make_float2(f2tf_f(acc[tm][tn][2] + c0),
                                     f2tf_f(acc[tm][tn][3] + c1));
            *(float2*)&g_Q[((size_t)b * NK + r) * DD + c]     = v0;
            *(float2*)&g_Q[((size_t)b * NK + r + 8) * DD + c] = v1s;
        }
    }
}

// ---------------------------------------------------------------------------
// Stage 2 (tf32 mma.sync, fp16 weights): per-mode complex GEMM.
// A (g_Q) in fp32/tf32, B (g_WtH) in fp16 scaled by 2^14; cscale /= 2^14.
// ---------------------------------------------------------------------------
#define S2_A_BYTES (64 * 36 * 4)      // 9216
#define S2_B_BYTES (64 * 136 * 2)     // 17408 (halves, pitch 136)
#define S2_BUF_BYTES (S2_A_BYTES + S2_B_BYTES)
#define S2_SMEM (2 * S2_BUF_BYTES)

__global__ __launch_bounds__(256) void fno_stage2_mma() {
    extern __shared__ char smc[];
    const int m  = blockIdx.y;
    const int e0 = blockIdx.x * 128;
    const int tid = threadIdx.x;
    const int warp = tid >> 5, lane = tid & 31;
    const int wm = warp >> 2;
    const int wn = warp & 3;
    const int gid = lane >> 2, tig = lane & 3;
    const uint32_t smem_u = (uint32_t)__cvta_generic_to_shared(smc);

    float accR[4][4], accI[4][4];
#pragma unroll
    for (int i = 0; i < 4; i++)
#pragma unroll
        for (int j = 0; j < 4; j++) { accR[i][j] = 0.0f; accI[i][j] = 0.0f; }

    auto load_tiles = [&](int buf, int d0) {
        uint32_t aB = smem_u + buf * S2_BUF_BYTES;
        uint32_t bB = aB + S2_A_BYTES;
        // A: 64 rows (ri*32+b) x 32 d floats
#pragma unroll
        for (int i = 0; i < 2; i++) {
            int idx = tid + i * 256;
            int row = idx >> 3, c4 = idx & 7;
            int ri = row >> 5, bb = row & 31;
            cp16(aB + (row * 36 + c4 * 4) * 4,
                 &g_Q[((size_t)bb * NK + ri * MODES + m) * DD + d0 + c4 * 4]);
        }
        // B: 64 rows (ri*32+d) x 128 e halves (16 cp16 of 8 halves per row)
#pragma unroll
        for (int i = 0; i < 4; i++) {
            int idx = tid + i * 256;
            int row = idx >> 4, c8 = idx & 15;
            int ri = row >> 5, dr = row & 31;
            cp16(bB + row * 272 + c8 * 16,
                 &g_WtH[(((size_t)ri * MODES + m) * DD + d0 + dr) * DD + e0 + c8 * 8]);
        }
        cp_commit();
    };

    load_tiles(0, 0);
    int buf = 0;
    const int NT = DD / 32;
    for (int kt = 0; kt < NT; kt++) {
        if (kt + 1 < NT) {
            load_tiles(buf ^ 1, (kt + 1) * 32);
            asm volatile("cp.async.wait_group 1;");
        } else {
            asm volatile("cp.async.wait_group 0;");
        }
        __syncthreads();
        const float*  As = (const float*)(smc + buf * S2_BUF_BYTES);
        const __half* Bs = (const __half*)(smc + buf * S2_BUF_BYTES + S2_A_BYTES);
#pragma unroll
        for (int ks = 0; ks < 4; ks++) {
            uint32_t ar[4], ai[4];
            {
                const float* ap = As + (wm * 16 + gid) * 36 + ks * 8 + tig;
                ar[0] = __float_as_uint(ap[0]);
                ar[1] = __float_as_uint(ap[8 * 36]);
                ar[2] = __float_as_uint(ap[4]);
                ar[3] = __float_as_uint(ap[8 * 36 + 4]);
                const float* aq = ap + 32 * 36;
                ai[0] = __float_as_uint(aq[0]);
                ai[1] = __float_as_uint(aq[8 * 36]);
                ai[2] = __float_as_uint(aq[4]);
                ai[3] = __float_as_uint(aq[8 * 36 + 4]);
            }
#pragma unroll
            for (int tn = 0; tn < 4; tn++) {
                const __half* bp = Bs + (ks * 8 + tig) * 136 + wn * 32 + tn * 8 + gid;
                float brf0 = __half2float(bp[0]);
                float brf1 = __half2float(bp[4 * 136]);
                float bif0 = __half2float(bp[32 * 136]);
                float bif1 = __half2float(bp[36 * 136]);
                uint32_t br0 = __float_as_uint(brf0);
                uint32_t br1 = __float_as_uint(brf1);
                uint32_t bi0 = __float_as_uint(-bif0);
                uint32_t bi1 = __float_as_uint(-bif1);
                mma_tf32(accR[tn], ar[0], ar[1], ar[2], ar[3], br0, br1);
                mma_tf32(accR[tn], ai[0], ai[1], ai[2], ai[3], bi0, bi1);
                mma_tf32(accI[tn], ar[0], ar[1], ar[2], ar[3],
                         bi0 ^ 0x80000000u, bi1 ^ 0x80000000u);
                mma_tf32(accI[tn], ai[0], ai[1], ai[2], ai[3], br0, br1);
            }
        }
        __syncthreads();
        buf ^= 1;
    }

    const float cscale = ((m == 0) ? (1.0f / (float)LL) : (2.0f / (float)LL)) / WSCALE;
#pragma unroll
    for (int tn = 0; tn < 4; tn++) {
        int c = e0 + wn * 32 + tn * 8 + tig * 2;
        int b0r = wm * 16 + gid;
        float2 r0 = make_float2(f2tf_f(cscale * accR[tn][0]), f2tf_f(cscale * accR[tn][1]));
        float2 r1 = make_float2(f2tf_f(cscale * accR[tn][2]), f2tf_f(cscale * accR[tn][3]));
        float2 i0 = make_float2(f2tf_f(cscale * accI[tn][0]), f2tf_f(cscale * accI[tn][1]));
        float2 i1 = make_float2(f2tf_f(cscale * accI[tn][2]), f2tf_f(cscale * accI[tn][3]));
        *(float2*)&g_Am[((size_t)b0r * NK + m) * DD + c]               = r0;
        *(float2*)&g_Am[((size_t)(b0r + 8) * NK + m) * DD + c]         = r1;
        *(float2*)&g_Am[((size_t)b0r * NK + MODES + m) * DD + c]       = i0;
        *(float2*)&g_Am[((size_t)(b0r + 8) * NK + MODES + m) * DD + c] = i1;
    }
}

// ===========================================================================
// Stage 3 (double-folded, tf32 MMA, BN=64)
// ===========================================================================
#define T3_ASZ (64 * 132)
#define T3_BSZ (128 * 72)
#define T3_SMEM ((T3_ASZ + T3_BSZ) * 4)    // 70656

__global__ __launch_bounds__(256, 2) void fno_stage3_fold2(float* __restrict__ out) {
    extern __shared__ float sm[];
    const int b  = blockIdx.z;
    const int l0 = blockIdx.y * 64;
    const int n0 = blockIdx.x * 64;
    const int tid = threadIdx.x;
    const int warp = tid >> 5, lane = tid & 31;
    const int wm = warp >> 2, wn = warp & 3;
    const int gid = lane >> 2, tig = lane & 3;
    const uint32_t smem_u = (uint32_t)__cvta_generic_to_shared(sm);
    const float* As = sm;
    const float* Bs = sm + T3_ASZ;

    {
        uint32_t aB = smem_u;
        uint32_t bB = smem_u + T3_ASZ * 4;
#pragma unroll
        for (int i = 0; i < 8; i++) {
            int idx = tid + i * 256;
            int row = idx >> 5, c4 = idx & 31;
            cp16(aB + (row * 132 + c4 * 4) * 4, &g_S3F[(l0 + row) * 128 + c4 * 4]);
        }
#pragma unroll
        for (int i = 0; i < 8; i++) {
            int idx = tid + i * 256;
            int row = idx >> 4, c4 = idx & 15;
            int ri = row >> 6, rr = row & 63;
            int srow = ri * 64 + ((rr & 31) << 1) + (rr >> 5);
            cp16(bB + (row * 72 + c4 * 4) * 4,
                 &g_Am[((size_t)b * NK + srow) * DD + n0 + c4 * 4]);
        }
        cp_commit();
        asm volatile("cp.async.wait_group 0;");
        __syncthreads();
    }

    float aCE[2][2][4], aCO[2][2][4], aSE[2][2][4], aSO[2][2][4];
#pragma unroll
    for (int i = 0; i < 2; i++)
#pragma unroll
        for (int j = 0; j < 2; j++)
#pragma unroll
            for (int k = 0; k < 4; k++) {
                aCE[i][j][k] = 0.0f; aCO[i][j][k] = 0.0f;
                aSE[i][j][k] = 0.0f; aSO[i][j][k] = 0.0f;
            }

#pragma unroll
    for (int ks = 0; ks < 16; ks++) {
        uint32_t a[2][4];
#pragma unroll
        for (int tm = 0; tm < 2; tm++) {
            const float* ap = As + (wm * 32 + tm * 16 + gid) * 132 + ks * 8 + tig;
            a[tm][0] = __float_as_uint(ap[0]);
            a[tm][1] = __float_as_uint(ap[8 * 132]);
            a[tm][2] = __float_as_uint(ap[4]);
            a[tm][3] = __float_as_uint(ap[8 * 132 + 4]);
        }
        uint32_t bf[2][2];
#pragma unroll
        for (int tn = 0; tn < 2; tn++) {
            const float* bp = Bs + (ks * 8 + tig) * 72 + wn * 16 + tn * 8 + gid;
            bf[tn][0] = __float_as_uint(bp[0]);
            bf[tn][1] = __float_as_uint(bp[4 * 72]);
        }
        if (ks < 4) {
#pragma unroll
            for (int tm = 0; tm < 2; tm++)
#pragma unroll
                for (int tn = 0; tn < 2; tn++)
                    mma_tf32(aCE[tm][tn], a[tm][0], a[tm][1], a[tm][2], a[tm][3],
                             bf[tn][0], bf[tn][1]);
        } else if (ks < 8) {
#pragma unroll
            for (int tm = 0; tm < 2; tm++)
#pragma unroll
                for (int tn = 0; tn < 2; tn++)
                    mma_tf32(aCO[tm][tn], a[tm][0], a[tm][1], a[tm][2], a[tm][3],
                             bf[tn][0], bf[tn][1]);
        } else if (ks < 12) {
#pragma unroll
            for (int tm = 0; tm < 2; tm++)
#pragma unroll
                for (int tn = 0; tn < 2; tn++)
                    mma_tf32(aSE[tm][tn], a[tm][0], a[tm][1], a[tm][2], a[tm][3],
                             bf[tn][0], bf[tn][1]);
        } else {
#pragma unroll
            for (int tm = 0; tm < 2; tm++)
#pragma unroll
                for (int tn = 0; tn < 2; tn++)
                    mma_tf32(aSO[tm][tn], a[tm][0], a[tm][1], a[tm][2], a[tm][3],
                             bf[tn][0], bf[tn][1]);
        }
    }

    float* ob = out + (size_t)b * LL * DD;
#pragma unroll
    for (int tm = 0; tm < 2; tm++) {
        int lA = l0 + wm * 32 + tm * 16 + gid;
#pragma unroll
        for (int tn = 0; tn < 2; tn++) {
            int c = n0 + wn * 16 + tn * 8 + tig * 2;
#pragma unroll
            for (int h = 0; h < 2; h++) {
                int l = lA + h * 8;
                float ce0 = aCE[tm][tn][h * 2],     ce1 = aCE[tm][tn][h * 2 + 1];
                float co0 = aCO[tm][tn][h * 2],     co1 = aCO[tm][tn][h * 2 + 1];
                float se0 = aSE[tm][tn][h * 2],     se1 = aSE[tm][tn][h * 2 + 1];
                float so0 = aSO[tm][tn][h * 2],     so1 = aSO[tm][tn][h * 2 + 1];
                *(float2*)&ob[(size_t)l * DD + c] =
                    make_float2(ce0 + co0 + se0 + so0, ce1 + co1 + se1 + so1);
                *(float2*)&ob[(size_t)(2048 - l) * DD + c] =
                    make_float2(ce0 - co0 - se0 + so0, ce1 - co1 - se1 + so1);
                *(float2*)&ob[(size_t)(2048 + l) * DD + c] =
                    make_float2(ce0 - co0 + se0 - so0, ce1 - co1 + se1 - so1);
                if (l > 0)
                    *(float2*)&ob[(size_t)(LL - l) * DD + c] =
                        make_float2(ce0 + co0 - se0 - so0, ce1 + co1 - se1 - so1);
            }
        }
    }
}

// ---------------------------------------------------------------------------
// Rows l=1024 and l=3072 (not covered by the double fold)
// ---------------------------------------------------------------------------
__global__ void fno_rows_special(float* __restrict__ out) {
    int b = blockIdx.y;
    int e = blockIdx.x * 128 + threadIdx.x;
    float C = 0.0f, S = 0.0f;
#pragma unroll
    for (int j = 0; j < 32; j++) {
        float sgn = (j & 1) ? -1.0f : 1.0f;
        C += sgn * g_Am[((size_t)b * NK + 2 * j) * DD + e];
        S -= sgn * g_Am[((size_t)b * NK + MODES + 2 * j + 1) * DD + e];
    }
    out[((size_t)b * LL + 1024) * DD + e] = C + S;
    out[((size_t)b * LL + 3072) * DD + e] = C - S;
}

// ---------------------------------------------------------------------------
// Launch: transpose forked onto side stream (overlaps stage1);
// rows_special forked onto side stream (overlaps stage3).
// ---------------------------------------------------------------------------
extern "C" void kernel_launch(void* const* d_in, const int* in_sizes, int n_in,
                              void* d_out, int out_size) {
    (void)in_sizes; (void)n_in; (void)out_size;
    const float* q  = (const float*)d_in[0];
    const float* wr = (const float*)d_in[1];
    const float* wi = (const float*)d_in[2];
    float* out = (float*)d_out;

    static bool init_done = false;
    static cudaStream_t s_side;
    static cudaEvent_t ev_fork, ev_join, ev_fork2, ev_join2;
    if (!init_done) {
        cudaFuncSetAttribute(fno_stage1_fold,
                             cudaFuncAttributeMaxDynamicSharedMemorySize, S1F_SMEM);
        cudaFuncSetAttribute(fno_stage2_mma,
                             cudaFuncAttributeMaxDynamicSharedMemorySize, S2_SMEM);
        cudaFuncSetAttribute(fno_stage3_fold2,
                             cudaFuncAttributeMaxDynamicSharedMemorySize, T3_SMEM);
        cudaStreamCreateWithFlags(&s_side, cudaStreamNonBlocking);
        cudaEventCreateWithFlags(&ev_fork, cudaEventDisableTiming);
        cudaEventCreateWithFlags(&ev_join, cudaEventDisableTiming);
        cudaEventCreateWithFlags(&ev_fork2, cudaEventDisableTiming);
        cudaEventCreateWithFlags(&ev_join2, cudaEventDisableTiming);
        init_done = true;
    }

    // main stream: tables (stage1/stage3 dependency)
    fno_init<<<(F1_CNT + S3F_CNT + 255) / 256, 256>>>();

    // fork: transpose on side stream, concurrent with stage1
    cudaEventRecord(ev_fork, 0);
    cudaStreamWaitEvent(s_side, ev_fork, 0);
    fno_transpose_w<<<dim3(16, 2, 512), dim3(32, 8), 0, s_side>>>(wr, wi);

    fno_stage1_fold<<<dim3(8, 32), 256, S1F_SMEM>>>(q);

    // join: stage2 needs both g_Q (main) and g_WtH (side)
    cudaEventRecord(ev_join, s_side);
    cudaStreamWaitEvent(0, ev_join, 0);

    fno_stage2_mma<<<dim3(4, 64), 256, S2_SMEM>>>();

    // fork: rows_special on side stream, concurrent with stage3
    cudaEventRecord(ev_fork2, 0);
    cudaStreamWaitEvent(s_side, ev_fork2, 0);
    fno_rows_special<<<dim3(4, 32), 128, 0, s_side>>>(out);

    fno_stage3_fold2<<<dim3(8, 16, 32), 256, T3_SMEM>>>(out);

    // join: out complete on main stream
    cudaEventRecord(ev_join2, s_side);
    cudaStreamWaitEvent(0, ev_join2, 0);
}

// round 11
// speedup vs baseline: 1.0566x; 1.0239x over previous
#include <cuda_runtime.h>
#include <cuda_bf16.h>
#include <cuda_fp16.h>
#include <cstdint>

// Problem constants
#define BB 32
#define LL 4096
#define DD 512
#define MODES 64
#define NK 128          // 2*MODES (real rows + imag rows)
#define WSCALE 16384.0f // 2^14 fp16 range scaling for weights
#define AMSCALE 33554432.0f   // 2^25 fp16 range scaling for spectra
#define INV_AMSCALE (1.0f / 33554432.0f)

// ---------------------------------------------------------------------------
// Static device scratch
// ---------------------------------------------------------------------------
__device__ float  g_F1[NK * 2048];               // folded fwd tables [128][2048], l=j+1 (tf32)
__device__ __half g_S3FH[1024 * 128];            // folded inv tables fp16 [l][c]: c<32 cosE,<64 cosO,<96 -sinE,<128 -sinO
__device__ __half g_WtH[2ull * MODES * DD * DD]; // [ri][m][d][e] fp16, scaled by 2^14
__device__ float  g_Q[BB * NK * DD];             // [b][row][d] (tf32)
__device__ __half g_AmH[BB * 64 * DD * 2];       // [b][p2][e][slot] fp16 spectra, permuted+pair-interleaved, x2^25

// ---------------------------------------------------------------------------
// Helpers
// ---------------------------------------------------------------------------
__device__ __forceinline__ uint32_t f2tf(float f) {
    uint32_t u;
    asm("cvt.rna.tf32.f32 %0, %1;" : "=r"(u) : "f"(f));
    return u;
}
__device__ __forceinline__ float f2tf_f(float f) { return __uint_as_float(f2tf(f)); }

__device__ __forceinline__ void mma_tf32(float c[4],
                                         uint32_t a0, uint32_t a1, uint32_t a2, uint32_t a3,
                                         uint32_t b0, uint32_t b1) {
    asm volatile(
        "mma.sync.aligned.m16n8k8.row.col.f32.tf32.tf32.f32 "
        "{%0,%1,%2,%3}, {%4,%5,%6,%7}, {%8,%9}, {%0,%1,%2,%3};"
        : "+f"(c[0]), "+f"(c[1]), "+f"(c[2]), "+f"(c[3])
        : "r"(a0), "r"(a1), "r"(a2), "r"(a3), "r"(b0), "r"(b1));
}

__device__ __forceinline__ void mma_f16(float c[4],
                                        uint32_t a0, uint32_t a1, uint32_t a2, uint32_t a3,
                                        uint32_t b0, uint32_t b1) {
    asm volatile(
        "mma.sync.aligned.m16n8k16.row.col.f32.f16.f16.f32 "
        "{%0,%1,%2,%3}, {%4,%5,%6,%7}, {%8,%9}, {%0,%1,%2,%3};"
        : "+f"(c[0]), "+f"(c[1]), "+f"(c[2]), "+f"(c[3])
        : "r"(a0), "r"(a1), "r"(a2), "r"(a3), "r"(b0), "r"(b1));
}

__device__ __forceinline__ void cp16(uint32_t dst_smem, const void* src) {
    asm volatile("cp.async.cg.shared.global [%0], [%1], 16;" :: "r"(dst_smem), "l"(src));
}
__device__ __forceinline__ void cp_commit() { asm volatile("cp.async.commit_group;"); }

// ---------------------------------------------------------------------------
// Init: all twiddle tables in one launch.
// ---------------------------------------------------------------------------
#define F1_CNT (NK * 2048)
#define S3F_CNT (1024 * 128)

__global__ void fno_init() {
    int idx = blockIdx.x * blockDim.x + threadIdx.x;
    if (idx < F1_CNT) {
        int row = idx >> 11;          // 0..127
        int j   = idx & 2047;
        int l   = j + 1;              // 1..2048
        int m   = row & (MODES - 1);
        int r   = (m * l) & (LL - 1);
        float s, c;
        sincospif((float)r * (1.0f / 2048.0f), &s, &c);
        g_F1[row * 2048 + j] = f2tf_f((row < MODES) ? c : -s);
    } else if (idx < F1_CNT + S3F_CNT) {
        int i2 = idx - F1_CNT;
        int l  = i2 >> 7;             // 0..1023
        int cc = i2 & 127;
        int grp = cc >> 5;            // 0 cosE, 1 cosO, 2 -sinE, 3 -sinO
        int m  = ((cc & 31) << 1) + (grp & 1);
        int r  = (m * l) & (LL - 1);
        float s, c;
        sincospif((float)r * (1.0f / 2048.0f), &s, &c);
        g_S3FH[l * 128 + cc] = __float2half_rn((grp < 2) ? c : -s);
    }
}

// ---------------------------------------------------------------------------
// Weight transpose: WtH[ri][m][d][e] = fp16(w_ri[d][e][m] * 2^14)
// ---------------------------------------------------------------------------
__global__ void fno_transpose_w(const float* __restrict__ wr,
                                const float* __restrict__ wi) {
    __shared__ float t[2][32][33];
    int d  = blockIdx.z;
    int e0 = blockIdx.x * 32;
    int m0 = blockIdx.y * 32;
    int tx = threadIdx.x, ty = threadIdx.y;
    size_t src_base = ((size_t)d * DD) * MODES + m0;
    for (int i = ty; i < 32; i += 8) {
        t[0][i][tx] = wr[src_base + (size_t)(e0 + i) * MODES + tx];
        t[1][i][tx] = wi[src_base + (size_t)(e0 + i) * MODES + tx];
    }
    __syncthreads();
    for (int i = ty; i < 32; i += 8) {
        size_t dst0 = (((size_t)(m0 + i)) * DD + d) * DD + e0 + tx;
        g_WtH[dst0]                           = __float2half_rn(t[0][tx][i] * WSCALE);
        g_WtH[dst0 + (size_t)MODES * DD * DD] = __float2half_rn(t[1][tx][i] * WSCALE);
    }
}

// ===========================================================================
// Stage 1 (folded, tf32 MMA, BN=64) — unchanged from R10.
// ===========================================================================
#define F1_A_F (128 * 36)
#define F1_B_F (32 * 72)
#define S1F_SMEM ((2 * F1_A_F + 4 * F1_B_F) * 4)   // 73728

__global__ __launch_bounds__(256, 2) void fno_stage1_fold(const float* __restrict__ q) {
    extern __shared__ float sm[];
    float* Bbase = sm + 2 * F1_A_F;
    const int b  = blockIdx.y;
    const int n0 = blockIdx.x * 64;
    const float* qb = q + (size_t)b * LL * DD;
    const int tid = threadIdx.x;
    const int warp = tid >> 5, lane = tid & 31;
    const int wm = warp >> 2, wn = warp & 3;
    const int gid = lane >> 2, tig = lane & 3;
    const uint32_t smu = (uint32_t)__cvta_generic_to_shared(sm);

    float acc[4][2][4];
#pragma unroll
    for (int i = 0; i < 4; i++)
#pragma unroll
        for (int j = 0; j < 2; j++)
#pragma unroll
            for (int k = 0; k < 4; k++) acc[i][j][k] = 0.0f;

    float4 v1[2], v2[2];
    auto ldB = [&](int k0) {
#pragma unroll
        for (int i = 0; i < 2; i++) {
            int idx = tid + i * 256;
            int j = idx >> 4, c4 = idx & 15;
            int l = k0 + j + 1;
            v1[i] = *(const float4*)&qb[(size_t)l * DD + n0 + c4 * 4];
            if (l == 2048) {
                v2[i] = make_float4(0.f, 0.f, 0.f, 0.f);
            } else {
                v2[i] = *(const float4*)&qb[(size_t)(LL - l) * DD + n0 + c4 * 4];
            }
        }
    };
    auto stB = [&](int buf) {
        float* P = Bbase + buf * 2 * F1_B_F;
        float* Dn = P + F1_B_F;
#pragma unroll
        for (int i = 0; i < 2; i++) {
            int idx = tid + i * 256;
            int j = idx >> 4, c4 = idx & 15;
            float4 p, d;
            p.x = f2tf_f(v1[i].x + v2[i].x);  d.x = f2tf_f(v1[i].x - v2[i].x);
            p.y = f2tf_f(v1[i].y + v2[i].y);  d.y = f2tf_f(v1[i].y - v2[i].y);
            p.z = f2tf_f(v1[i].z + v2[i].z);  d.z = f2tf_f(v1[i].z - v2[i].z);
            p.w = f2tf_f(v1[i].w + v2[i].w);  d.w = f2tf_f(v1[i].w - v2[i].w);
            *(float4*)&P[j * 72 + c4 * 4]  = p;
            *(float4*)&Dn[j * 72 + c4 * 4] = d;
        }
    };
    auto cpA = [&](int buf, int k0) {
        uint32_t aB = smu + buf * F1_A_F * 4;
#pragma unroll
        for (int i = 0; i < 4; i++) {
            int idx = tid + i * 256;
            int row = idx >> 3, c4 = idx & 7;
            cp16(aB + (row * 36 + c4 * 4) * 4, &g_F1[row * 2048 + k0 + c4 * 4]);
        }
        cp_commit();
    };

    cpA(0, 0);
    ldB(0);
    const int NT = 64;
    for (int kt = 0; kt < NT; kt++) {
        int buf = kt & 1;
        stB(buf);
        if (kt + 1 < NT) {
            cpA(buf ^ 1, (kt + 1) * 32);
            asm volatile("cp.async.wait_group 1;");
        } else {
            asm volatile("cp.async.wait_group 0;");
        }
        __syncthreads();
        if (kt + 1 < NT) ldB((kt + 1) * 32);

        const float* As = sm + buf * F1_A_F;
        const float* Bs = Bbase + buf * 2 * F1_B_F + wm * F1_B_F;  // P or D
#pragma unroll
        for (int ks = 0; ks < 4; ks++) {
            uint32_t a[4][4];
#pragma unroll
            for (int tm = 0; tm < 4; tm++) {
                const float* ap = As + (wm * 64 + tm * 16 + gid) * 36 + ks * 8 + tig;
                a[tm][0] = __float_as_uint(ap[0]);
                a[tm][1] = __float_as_uint(ap[8 * 36]);
                a[tm][2] = __float_as_uint(ap[4]);
                a[tm][3] = __float_as_uint(ap[8 * 36 + 4]);
            }
            uint32_t bf[2][2];
#pragma unroll
            for (int tn = 0; tn < 2; tn++) {
                const float* bp = Bs + (ks * 8 + tig) * 72 + wn * 16 + tn * 8 + gid;
                bf[tn][0] = __float_as_uint(bp[0]);
                bf[tn][1] = __float_as_uint(bp[4 * 72]);
            }
#pragma unroll
            for (int tm = 0; tm < 4; tm++)
#pragma unroll
                for (int tn = 0; tn < 2; tn++)
                    mma_tf32(acc[tm][tn], a[tm][0], a[tm][1], a[tm][2], a[tm][3],
                             bf[tn][0], bf[tn][1]);
        }
        __syncthreads();
    }

#pragma unroll
    for (int tm = 0; tm < 4; tm++) {
        int r = wm * 64 + tm * 16 + gid;
#pragma unroll
        for (int tn = 0; tn < 2; tn++) {
            int c = n0 + wn * 16 + tn * 8 + tig * 2;
            float c0 = 0.f, c1 = 0.f;
            if (wm == 0) { c0 = qb[c]; c1 = qb[c + 1]; }
            float2 v0 = make_float2(f2tf_f(acc[tm][tn][0] + c0),
                                    f2tf_f(acc[tm][tn][1] + c1));
            float2 v1s = make_float2(f2tf_f(acc[tm][tn][2] + c0),
                                     f2tf_f(acc[tm][tn][3] + c1));
            *(float2*)&g_Q[((size_t)b * NK + r) * DD + c]     = v0;
            *(float2*)&g_Q[((size_t)b * NK + r + 8) * DD + c] = v1s;
        }
    }
}

// ---------------------------------------------------------------------------
// Stage 2 (tf32 mma.sync, fp16 weights): per-mode complex GEMM.
// Epilogue writes g_AmH (fp16, stage3-permuted pair-interleaved, x2^25).
// ---------------------------------------------------------------------------
#define S2_A_BYTES (64 * 36 * 4)      // 9216
#define S2_B_BYTES (64 * 136 * 2)     // 17408 (halves, pitch 136)
#define S2_BUF_BYTES (S2_A_BYTES + S2_B_BYTES)
#define S2_SMEM (2 * S2_BUF_BYTES)

__global__ __launch_bounds__(256) void fno_stage2_mma() {
    extern __shared__ char smc[];
    const int m  = blockIdx.y;
    const int e0 = blockIdx.x * 128;
    const int tid = threadIdx.x;
    const int warp = tid >> 5, lane = tid & 31;
    const int wm = warp >> 2;
    const int wn = warp & 3;
    const int gid = lane >> 2, tig = lane & 3;
    const uint32_t smem_u = (uint32_t)__cvta_generic_to_shared(smc);

    float accR[4][4], accI[4][4];
#pragma unroll
    for (int i = 0; i < 4; i++)
#pragma unroll
        for (int j = 0; j < 4; j++) { accR[i][j] = 0.0f; accI[i][j] = 0.0f; }

    auto load_tiles = [&](int buf, int d0) {
        uint32_t aB = smem_u + buf * S2_BUF_BYTES;
        uint32_t bB = aB + S2_A_BYTES;
#pragma unroll
        for (int i = 0; i < 2; i++) {
            int idx = tid + i * 256;
            int row = idx >> 3, c4 = idx & 7;
            int ri = row >> 5, bb = row & 31;
            cp16(aB + (row * 36 + c4 * 4) * 4,
                 &g_Q[((size_t)bb * NK + ri * MODES + m) * DD + d0 + c4 * 4]);
        }
#pragma unroll
        for (int i = 0; i < 4; i++) {
            int idx = tid + i * 256;
            int row = idx >> 4, c8 = idx & 15;
            int ri = row >> 5, dr = row & 31;
            cp16(bB + row * 272 + c8 * 16,
                 &g_WtH[(((size_t)ri * MODES + m) * DD + d0 + dr) * DD + e0 + c8 * 8]);
        }
        cp_commit();
    };

    load_tiles(0, 0);
    int buf = 0;
    const int NT = DD / 32;
    for (int kt = 0; kt < NT; kt++) {
        if (kt + 1 < NT) {
            load_tiles(buf ^ 1, (kt + 1) * 32);
            asm volatile("cp.async.wait_group 1;");
        } else {
            asm volatile("cp.async.wait_group 0;");
        }
        __syncthreads();
        const float*  As = (const float*)(smc + buf * S2_BUF_BYTES);
        const __half* Bs = (const __half*)(smc + buf * S2_BUF_BYTES + S2_A_BYTES);
#pragma unroll
        for (int ks = 0; ks < 4; ks++) {
            uint32_t ar[4], ai[4];
            {
                const float* ap = As + (wm * 16 + gid) * 36 + ks * 8 + tig;
                ar[0] = __float_as_uint(ap[0]);
                ar[1] = __float_as_uint(ap[8 * 36]);
                ar[2] = __float_as_uint(ap[4]);
                ar[3] = __float_as_uint(ap[8 * 36 + 4]);
                const float* aq = ap + 32 * 36;
                ai[0] = __float_as_uint(aq[0]);
                ai[1] = __float_as_uint(aq[8 * 36]);
                ai[2] = __float_as_uint(aq[4]);
                ai[3] = __float_as_uint(aq[8 * 36 + 4]);
            }
#pragma unroll
            for (int tn = 0; tn < 4; tn++) {
                const __half* bp = Bs + (ks * 8 + tig) * 136 + wn * 32 + tn * 8 + gid;
                float brf0 = __half2float(bp[0]);
                float brf1 = __half2float(bp[4 * 136]);
                float bif0 = __half2float(bp[32 * 136]);
                float bif1 = __half2float(bp[36 * 136]);
                uint32_t br0 = __float_as_uint(brf0);
                uint32_t br1 = __float_as_uint(brf1);
                uint32_t bi0 = __float_as_uint(-bif0);
                uint32_t bi1 = __float_as_uint(-bif1);
                mma_tf32(accR[tn], ar[0], ar[1], ar[2], ar[3], br0, br1);
                mma_tf32(accR[tn], ai[0], ai[1], ai[2], ai[3], bi0, bi1);
                mma_tf32(accI[tn], ar[0], ar[1], ar[2], ar[3],
                         bi0 ^ 0x80000000u, bi1 ^ 0x80000000u);
                mma_tf32(accI[tn], ai[0], ai[1], ai[2], ai[3], br0, br1);
            }
        }
        __syncthreads();
        buf ^= 1;
    }

    // epilogue: write fp16 spectra in stage3 layout.
    // permuted row pr: even m -> m/2 (cos-even grp), odd m -> 32+m/2 ; +64 for imag.
    const float cfac = ((m == 0) ? 1.0f : 2.0f) * (AMSCALE / ((float)LL * WSCALE));
    const int mh  = m >> 1;
    const int pr  = (m & 1) ? (32 + mh) : mh;
    const int pi  = pr + 64;
    const int p2r = pr >> 1, slr = pr & 1;
    const int p2i = pi >> 1, sli = pi & 1;
#pragma unroll
    for (int tn = 0; tn < 4; tn++) {
        int c = e0 + wn * 32 + tn * 8 + tig * 2;
        int b0r = wm * 16 + gid;
#pragma unroll
        for (int h = 0; h < 2; h++) {
            int bb = b0r + h * 8;
            size_t baseR = (((size_t)bb * 64 + p2r) * DD) * 2 + slr;
            size_t baseI = (((size_t)bb * 64 + p2i) * DD) * 2 + sli;
            g_AmH[baseR + (size_t)(c)     * 2] = __float2half_rn(cfac * accR[tn][h * 2]);
            g_AmH[baseR + (size_t)(c + 1) * 2] = __float2half_rn(cfac * accR[tn][h * 2 + 1]);
            g_AmH[baseI + (size_t)(c)     * 2] = __float2half_rn(cfac * accI[tn][h * 2]);
            g_AmH[baseI + (size_t)(c + 1) * 2] = __float2half_rn(cfac * accI[tn][h * 2 + 1]);
        }
    }
}

// ===========================================================================
// Stage 3 (double-folded, fp16 MMA m16n8k16): for l in [0,1024):
//   out[l] = CE+CO+SE+SO ; out[2048-l] = CE-CO-SE+SO
//   out[2048+l] = CE-CO+SE-SO ; out[4096-l] = CE+CO-SE-SO (l>0)
// grid (8 e-tiles, 16 l-tiles, 32 b), block 256. BM=64(l) BN=64(e) K=128.
// A: g_S3FH fp16 [64][128]; B: g_AmH half2-pair rows [64 p2][64 e].
// ===========================================================================
#define T3H_A_BYTES (64 * 272)     // 17408 (64 rows x 136 halves)
#define T3H_B_BYTES (64 * 272)     // 17408 (64 p2-rows x 68 half2)
#define T3H_SMEM (T3H_A_BYTES + T3H_B_BYTES)   // 34816

__global__ __launch_bounds__(256, 2) void fno_stage3_fold2(float* __restrict__ out) {
    extern __shared__ char smc[];
    const int b  = blockIdx.z;
    const int l0 = blockIdx.y * 64;
    const int n0 = blockIdx.x * 64;
    const int tid = threadIdx.x;
    const int warp = tid >> 5, lane = tid & 31;
    const int wm = warp >> 2, wn = warp & 3;      // wm 0..1 (32 l-rows), wn 0..3 (16 e)
    const int gid = lane >> 2, tig = lane & 3;
    const uint32_t smem_u = (uint32_t)__cvta_generic_to_shared(smc);
    const char* As = smc;
    const char* Bs = smc + T3H_A_BYTES;
    const __half2* gah = (const __half2*)g_AmH;

    {
        uint32_t aB = smem_u;
        uint32_t bB = smem_u + T3H_A_BYTES;
#pragma unroll
        for (int i = 0; i < 4; i++) {      // A: 64 rows x 128 halves (16 cp16/row)
            int idx = tid + i * 256;
            int row = idx >> 4, c16 = idx & 15;
            cp16(aB + row * 272 + c16 * 16, &g_S3FH[(l0 + row) * 128 + c16 * 8]);
        }
#pragma unroll
        for (int i = 0; i < 4; i++) {      // B: 64 p2-rows x 64 half2 (16 cp16/row)
            int idx = tid + i * 256;
            int row = idx >> 4, c4 = idx & 15;
            cp16(bB + row * 272 + c4 * 16,
                 &gah[((size_t)(b * 64 + row)) * DD + n0 + c4 * 4]);
        }
        cp_commit();
        asm volatile("cp.async.wait_group 0;");
        __syncthreads();
    }

    float aCE[2][2][4], aCO[2][2][4], aSE[2][2][4], aSO[2][2][4];
#pragma unroll
    for (int i = 0; i < 2; i++)
#pragma unroll
        for (int j = 0; j < 2; j++)
#pragma unroll
            for (int k = 0; k < 4; k++) {
                aCE[i][j][k] = 0.0f; aCO[i][j][k] = 0.0f;
                aSE[i][j][k] = 0.0f; aSO[i][j][k] = 0.0f;
            }

#pragma unroll
    for (int ks = 0; ks < 8; ks++) {       // K=16 per step
        uint32_t a[2][4];
#pragma unroll
        for (int tm = 0; tm < 2; tm++) {
            const char* ap = As + (wm * 32 + tm * 16 + gid) * 272 + (ks * 16 + 2 * tig) * 2;
            a[tm][0] = *(const uint32_t*)(ap);
            a[tm][1] = *(const uint32_t*)(ap + 8 * 272);
            a[tm][2] = *(const uint32_t*)(ap + 16);
            a[tm][3] = *(const uint32_t*)(ap + 8 * 272 + 16);
        }
        uint32_t bf[2][2];
#pragma unroll
        for (int tn = 0; tn < 2; tn++) {
            const char* bp = Bs + (ks * 8 + tig) * 272 + (wn * 16 + tn * 8 + gid) * 4;
            bf[tn][0] = *(const uint32_t*)(bp);
            bf[tn][1] = *(const uint32_t*)(bp + 4 * 272);
        }
        if (ks < 2) {
#pragma unroll
            for (int tm = 0; tm < 2; tm++)
#pragma unroll
                for (int tn = 0; tn < 2; tn++)
                    mma_f16(aCE[tm][tn], a[tm][0], a[tm][1], a[tm][2], a[tm][3],
                            bf[tn][0], bf[tn][1]);
        } else if (ks < 4) {
#pragma unroll
            for (int tm = 0; tm < 2; tm++)
#pragma unroll
                for (int tn = 0; tn < 2; tn++)
                    mma_f16(aCO[tm][tn], a[tm][0], a[tm][1], a[tm][2], a[tm][3],
                            bf[tn][0], bf[tn][1]);
        } else if (ks < 6) {
#pragma unroll
            for (int tm = 0; tm < 2; tm++)
#pragma unroll
                for (int tn = 0; tn < 2; tn++)
                    mma_f16(aSE[tm][tn], a[tm][0], a[tm][1], a[tm][2], a[tm][3],
                            bf[tn][0], bf[tn][1]);
        } else {
#pragma unroll
            for (int tm = 0; tm < 2; tm++)
#pragma unroll
                for (int tn = 0; tn < 2; tn++)
                    mma_f16(aSO[tm][tn], a[tm][0], a[tm][1], a[tm][2], a[tm][3],
                            bf[tn][0], bf[tn][1]);
        }
    }

    float* ob = out + (size_t)b * LL * DD;
#pragma unroll
    for (int tm = 0; tm < 2; tm++) {
        int lA = l0 + wm * 32 + tm * 16 + gid;
#pragma unroll
        for (int tn = 0; tn < 2; tn++) {
            int c = n0 + wn * 16 + tn * 8 + tig * 2;
#pragma unroll
            for (int h = 0; h < 2; h++) {
                int l = lA + h * 8;
                float ce0 = aCE[tm][tn][h * 2],     ce1 = aCE[tm][tn][h * 2 + 1];
                float co0 = aCO[tm][tn][h * 2],     co1 = aCO[tm][tn][h * 2 + 1];
                float se0 = aSE[tm][tn][h * 2],     se1 = aSE[tm][tn][h * 2 + 1];
                float so0 = aSO[tm][tn][h * 2],     so1 = aSO[tm][tn][h * 2 + 1];
                *(float2*)&ob[(size_t)l * DD + c] =
                    make_float2((ce0 + co0 + se0 + so0) * INV_AMSCALE,
                                (ce1 + co1 + se1 + so1) * INV_AMSCALE);
                *(float2*)&ob[(size_t)(2048 - l) * DD + c] =
                    make_float2((ce0 - co0 - se0 + so0) * INV_AMSCALE,
                                (ce1 - co1 - se1 + so1) * INV_AMSCALE);
                *(float2*)&ob[(size_t)(2048 + l) * DD + c] =
                    make_float2((ce0 - co0 + se0 - so0) * INV_AMSCALE,
                                (ce1 - co1 + se1 - so1) * INV_AMSCALE);
                if (l > 0)
                    *(float2*)&ob[(size_t)(LL - l) * DD + c] =
                        make_float2((ce0 + co0 - se0 - so0) * INV_AMSCALE,
                                    (ce1 + co1 - se1 - so1) * INV_AMSCALE);
            }
        }
    }
}

// ---------------------------------------------------------------------------
// Rows l=1024 and l=3072 (not covered by the double fold)
//   C = sum_j (-1)^j Amr[2j] ; S = -sum_j (-1)^j Ami[2j+1]
// Amr[2j]  : pr = j      -> p2 = j>>1,      slot = j&1
// Ami[2j+1]: p  = 96 + j -> p2 = 48+(j>>1), slot = j&1
// ---------------------------------------------------------------------------
__global__ void fno_rows_special(float* __restrict__ out) {
    int b = blockIdx.y;
    int e = blockIdx.x * 128 + threadIdx.x;
    float C = 0.0f, S = 0.0f;
#pragma unroll
    for (int j = 0; j < 32; j++) {
        float sgn = (j & 1) ? -1.0f : 1.0f;
        float ar = __half2float(g_AmH[(((size_t)b * 64 + (j >> 1)) * DD + e) * 2 + (j & 1)]);
        float ai = __half2float(g_AmH[(((size_t)b * 64 + 48 + (j >> 1)) * DD + e) * 2 + (j & 1)]);
        C += sgn * ar;
        S -= sgn * ai;
    }
    out[((size_t)b * LL + 1024) * DD + e] = (C + S) * INV_AMSCALE;
    out[((size_t)b * LL + 3072) * DD + e] = (C - S) * INV_AMSCALE;
}

// ---------------------------------------------------------------------------
// Launch: transpose forked onto side stream (overlaps stage1);
// rows_special forked onto side stream (overlaps stage3).
// ---------------------------------------------------------------------------
extern "C" void kernel_launch(void* const* d_in, const int* in_sizes, int n_in,
                              void* d_out, int out_size) {
    (void)in_sizes; (void)n_in; (void)out_size;
    const float* q  = (const float*)d_in[0];
    const float* wr = (const float*)d_in[1];
    const float* wi = (const float*)d_in[2];
    float* out = (float*)d_out;

    static bool init_done = false;
    static cudaStream_t s_side;
    static cudaEvent_t ev_fork, ev_join, ev_fork2, ev_join2;
    if (!init_done) {
        cudaFuncSetAttribute(fno_stage1_fold,
                             cudaFuncAttributeMaxDynamicSharedMemorySize, S1F_SMEM);
        cudaFuncSetAttribute(fno_stage2_mma,
                             cudaFuncAttributeMaxDynamicSharedMemorySize, S2_SMEM);
        cudaFuncSetAttribute(fno_stage3_fold2,
                             cudaFuncAttributeMaxDynamicSharedMemorySize, T3H_SMEM);
        cudaStreamCreateWithFlags(&s_side, cudaStreamNonBlocking);
        cudaEventCreateWithFlags(&ev_fork, cudaEventDisableTiming);
        cudaEventCreateWithFlags(&ev_join, cudaEventDisableTiming);
        cudaEventCreateWithFlags(&ev_fork2, cudaEventDisableTiming);
        cudaEventCreateWithFlags(&ev_join2, cudaEventDisableTiming);
        init_done = true;
    }

    // main stream: tables (stage1/stage3 dependency)
    fno_init<<<(F1_CNT + S3F_CNT + 255) / 256, 256>>>();

    // fork: transpose on side stream, concurrent with stage1
    cudaEventRecord(ev_fork, 0);
    cudaStreamWaitEvent(s_side, ev_fork, 0);
    fno_transpose_w<<<dim3(16, 2, 512), dim3(32, 8), 0, s_side>>>(wr, wi);

    fno_stage1_fold<<<dim3(8, 32), 256, S1F_SMEM>>>(q);

    // join: stage2 needs both g_Q (main) and g_WtH (side)
    cudaEventRecord(ev_join, s_side);
    cudaStreamWaitEvent(0, ev_join, 0);

    fno_stage2_mma<<<dim3(4, 64), 256, S2_SMEM>>>();

    // fork: rows_special on side stream, concurrent with stage3
    cudaEventRecord(ev_fork2, 0);
    cudaStreamWaitEvent(s_side, ev_fork2, 0);
    fno_rows_special<<<dim3(4, 32), 128, 0, s_side>>>(out);

    fno_stage3_fold2<<<dim3(8, 16, 32), 256, T3H_SMEM>>>(out);

    // join: out complete on main stream
    cudaEventRecord(ev_join2, s_side);
    cudaStreamWaitEvent(0, ev_join2, 0);
}